// round 7
// baseline (speedup 1.0000x reference)
#include <cuda_runtime.h>
#include <cstdint>

// Problem constants (GCNLayer_12317966205308)
#define NN 50000
#define EE 800000
#define D  64

// Scratch (device globals; no allocs allowed)
__device__ __align__(256) float g_xws[NN * D];   // dis[j] * (x[j] @ W)
__device__ __align__(256) float g_dis[NN];       // rsqrt(deg)
__device__ __align__(256) int   g_ecnt[NN];      // edge count per dst (no self loop)
__device__ __align__(256) int   g_row[NN + 1];   // CSR row offsets
__device__ __align__(256) int   g_cur[NN];       // write cursors for permute
__device__ __align__(256) int   g_ssrc[EE];      // src indices grouped by dst

// ---------------------------------------------------------------------------
// K1: zero edge-count histogram
__global__ void k_zero(int n) {
    int i = blockIdx.x * blockDim.x + threadIdx.x;
    if (i < n) g_ecnt[i] = 0;
}

// K2: histogram over edge targets, 4 edges/thread via int4
__global__ void k_hist(const int* __restrict__ ei, int E) {
    int q = blockIdx.x * blockDim.x + threadIdx.x;
    int e0 = q * 4;
    if (e0 + 4 <= E) {
        int4 d = *reinterpret_cast<const int4*>(ei + E + e0);
        atomicAdd(&g_ecnt[d.x], 1);
        atomicAdd(&g_ecnt[d.y], 1);
        atomicAdd(&g_ecnt[d.z], 1);
        atomicAdd(&g_ecnt[d.w], 1);
    } else {
        for (int e = e0; e < E; e++) atomicAdd(&g_ecnt[ei[E + e]], 1);
    }
}

// K3: single-block exclusive scan of g_ecnt -> g_row[0..n], g_cur = g_row.
// 1024 threads, each owns a contiguous chunk; int4 loads; Hillis-Steele
// block scan of per-thread totals.
#define SCAN_T 1024
__global__ void __launch_bounds__(SCAN_T) k_scan(int n) {
    __shared__ int sums[SCAN_T];
    int t = threadIdx.x;
    int chunk = ((n + SCAN_T - 1) / SCAN_T + 3) & ~3;   // mult of 4
    int lo = t * chunk;
    int hi = lo + chunk; if (hi > n) hi = n;

    int run = 0;
    int j = lo;
    for (; j + 4 <= hi; j += 4) {
        int4 v = *reinterpret_cast<const int4*>(g_ecnt + j);   // lo%4==0, n%4==0
        g_row[j + 0] = run; run += v.x;
        g_row[j + 1] = run; run += v.y;
        g_row[j + 2] = run; run += v.z;
        g_row[j + 3] = run; run += v.w;
    }
    for (; j < hi; j++) { g_row[j] = run; run += g_ecnt[j]; }

    sums[t] = run;
    __syncthreads();
    // in-place inclusive Hillis-Steele
    for (int off = 1; off < SCAN_T; off <<= 1) {
        int y = (t >= off) ? sums[t - off] : 0;
        __syncthreads();
        sums[t] += y;
        __syncthreads();
    }
    int offset = sums[t] - run;   // exclusive prefix of this thread's chunk
    for (j = lo; j < hi; j++) {
        int r = g_row[j] + offset;
        g_row[j] = r;
        g_cur[j] = r;
    }
    if (t == SCAN_T - 1) g_row[n] = sums[SCAN_T - 1];
}

// K4: permute srcs into dst-grouped order
__global__ void k_permute(const int* __restrict__ ei, int E) {
    int q = blockIdx.x * blockDim.x + threadIdx.x;
    int e0 = q * 4;
    if (e0 + 4 <= E) {
        int4 s = *reinterpret_cast<const int4*>(ei + e0);
        int4 d = *reinterpret_cast<const int4*>(ei + E + e0);
        g_ssrc[atomicAdd(&g_cur[d.x], 1)] = s.x;
        g_ssrc[atomicAdd(&g_cur[d.y], 1)] = s.y;
        g_ssrc[atomicAdd(&g_cur[d.z], 1)] = s.z;
        g_ssrc[atomicAdd(&g_cur[d.w], 1)] = s.w;
    } else {
        for (int e = e0; e < E; e++)
            g_ssrc[atomicAdd(&g_cur[ei[E + e]], 1)] = ei[e];
    }
}

// K5: xws = dis * (x @ W); store dis. deg = ecnt + 1 (self loop).
// 256 threads/block, 64 rows/block, 4x4 register tile per thread.
__global__ void __launch_bounds__(256) k_xw(const float* __restrict__ x,
                                            const float* __restrict__ W, int n) {
    __shared__ float Ws[D * D];        // [k][c]
    __shared__ float xs[64][D + 1];    // [r][k], padded
    int tid = threadIdx.x;
    int row0 = blockIdx.x * 64;

    {
        const float4* W4 = (const float4*)W;
        float4* Ws4 = (float4*)Ws;
        #pragma unroll
        for (int i = 0; i < 4; i++) Ws4[tid + 256 * i] = W4[tid + 256 * i];
    }
    #pragma unroll
    for (int i = 0; i < 4; i++) {
        int f = tid + 256 * i;
        int r = f >> 4, c4 = f & 15;
        int node = row0 + r;
        float4 v = (node < n) ? ((const float4*)(x + (size_t)node * D))[c4]
                              : make_float4(0.f, 0.f, 0.f, 0.f);
        xs[r][c4 * 4 + 0] = v.x; xs[r][c4 * 4 + 1] = v.y;
        xs[r][c4 * 4 + 2] = v.z; xs[r][c4 * 4 + 3] = v.w;
    }
    __syncthreads();

    int cg = tid & 15;   // cols [cg*4, cg*4+4)
    int rg = tid >> 4;   // rows [rg*4, rg*4+4)
    float acc[4][4] = {};
    #pragma unroll 4
    for (int k = 0; k < D; k++) {
        float4 w = *(const float4*)&Ws[k * D + cg * 4];
        #pragma unroll
        for (int rr = 0; rr < 4; rr++) {
            float xv = xs[rg * 4 + rr][k];
            acc[rr][0] = fmaf(xv, w.x, acc[rr][0]);
            acc[rr][1] = fmaf(xv, w.y, acc[rr][1]);
            acc[rr][2] = fmaf(xv, w.z, acc[rr][2]);
            acc[rr][3] = fmaf(xv, w.w, acc[rr][3]);
        }
    }

    #pragma unroll
    for (int rr = 0; rr < 4; rr++) {
        int node = row0 + rg * 4 + rr;
        if (node < n) {
            float dis = rsqrtf((float)(g_ecnt[node] + 1));
            float4 v = make_float4(dis * acc[rr][0], dis * acc[rr][1],
                                   dis * acc[rr][2], dis * acc[rr][3]);
            ((float4*)(g_xws + (size_t)node * D))[cg] = v;
            if (cg == 0) g_dis[node] = dis;
        }
    }
}

// K6: gather-aggregate + bias + relu. 16 threads per dst node; neighbor rows
// accumulated in registers, one float4 store per lane. No atomics.
__global__ void __launch_bounds__(256) k_agg(const float* __restrict__ b,
                                             float* __restrict__ out, int n) {
    int t = blockIdx.x * blockDim.x + threadIdx.x;
    int i = t >> 4;
    int lane = t & 15;
    if (i >= n) return;
    const float4* X = (const float4*)g_xws;

    float4 acc = X[(size_t)i * 16 + lane];   // self-loop term
    int e = g_row[i], end = g_row[i + 1];
    for (; e + 4 <= end; e += 4) {
        int s0 = g_ssrc[e], s1 = g_ssrc[e + 1];
        int s2 = g_ssrc[e + 2], s3 = g_ssrc[e + 3];
        float4 a0 = X[(size_t)s0 * 16 + lane];
        float4 a1 = X[(size_t)s1 * 16 + lane];
        float4 a2 = X[(size_t)s2 * 16 + lane];
        float4 a3 = X[(size_t)s3 * 16 + lane];
        acc.x += (a0.x + a1.x) + (a2.x + a3.x);
        acc.y += (a0.y + a1.y) + (a2.y + a3.y);
        acc.z += (a0.z + a1.z) + (a2.z + a3.z);
        acc.w += (a0.w + a1.w) + (a2.w + a3.w);
    }
    for (; e < end; e++) {
        int s = g_ssrc[e];
        float4 a = X[(size_t)s * 16 + lane];
        acc.x += a.x; acc.y += a.y; acc.z += a.z; acc.w += a.w;
    }

    float dis = g_dis[i];
    float4 bb = ((const float4*)b)[lane];
    float4 o;
    o.x = fmaxf(fmaf(dis, acc.x, bb.x), 0.0f);
    o.y = fmaxf(fmaf(dis, acc.y, bb.y), 0.0f);
    o.z = fmaxf(fmaf(dis, acc.z, bb.z), 0.0f);
    o.w = fmaxf(fmaf(dis, acc.w, bb.w), 0.0f);
    ((float4*)out)[t] = o;
}

// ---------------------------------------------------------------------------
extern "C" void kernel_launch(void* const* d_in, const int* in_sizes, int n_in,
                              void* d_out, int out_size) {
    const float* x  = (const float*)d_in[0];   // [N, 64] f32
    const int*   ei = (const int*)d_in[1];     // [2, E] int32
    const float* W  = (const float*)d_in[2];   // [64, 64] f32
    const float* b  = (const float*)d_in[3];   // [64] f32
    float* out = (float*)d_out;

    int N = in_sizes[0] / D;
    int E = in_sizes[1] / 2;
    int quads = (E + 3) / 4;

    k_zero<<<(N + 255) / 256, 256>>>(N);
    k_hist<<<(quads + 255) / 256, 256>>>(ei, E);
    k_scan<<<1, SCAN_T>>>(N);
    k_permute<<<(quads + 255) / 256, 256>>>(ei, E);
    k_xw<<<(N + 63) / 64, 256>>>(x, W, N);
    {
        int work = N * 16;
        k_agg<<<(work + 255) / 256, 256>>>(b, out, N);
    }
}

// round 8
// speedup vs baseline: 1.9773x; 1.9773x over previous
#include <cuda_runtime.h>
#include <cuda_fp16.h>
#include <cstdint>

// Problem constants (GCNLayer_12317966205308)
#define NN 50000
#define EE 800000
#define D  64

__device__ __align__(256) float  g_acc[NN * D];   // accumulator (init = self-loop term, f32)
__device__ __align__(256) __half g_xwsh[NN * D];  // fp16 copy of dis[j]*(x[j]@W) for gather
__device__ __align__(256) float  g_dis[NN];       // rsqrt(deg)
__device__ __align__(256) int    g_deg[NN];

// ---------------------------------------------------------------------------
// K1: deg init = 1 (self loop)
__global__ void k_deg_init(int n) {
    int i = blockIdx.x * blockDim.x + threadIdx.x;
    if (i < n) g_deg[i] = 1;
}

// K2: deg count over edge targets, 4 edges/thread via int4
__global__ void k_deg_count(const int* __restrict__ ei, int E) {
    int q = blockIdx.x * blockDim.x + threadIdx.x;
    int e0 = q * 4;
    if (e0 + 4 <= E) {
        int4 d = *reinterpret_cast<const int4*>(ei + E + e0);   // E % 4 == 0
        atomicAdd(&g_deg[d.x], 1);
        atomicAdd(&g_deg[d.y], 1);
        atomicAdd(&g_deg[d.z], 1);
        atomicAdd(&g_deg[d.w], 1);
    } else {
        for (int e = e0; e < E; e++) atomicAdd(&g_deg[ei[E + e]], 1);
    }
}

// K3: v = dis * (x @ W); acc = v (f32, self-loop term); xwsh = half(v); store dis.
// 256 threads/block, 64 rows/block, 4x4 register tile per thread.
__global__ void __launch_bounds__(256) k_xw(const float* __restrict__ x,
                                            const float* __restrict__ W, int n) {
    __shared__ float Ws[D * D];        // [k][c]
    __shared__ float xs[64][D + 1];    // [r][k], padded
    int tid = threadIdx.x;
    int row0 = blockIdx.x * 64;

    {
        const float4* W4 = (const float4*)W;
        float4* Ws4 = (float4*)Ws;
        #pragma unroll
        for (int i = 0; i < 4; i++) Ws4[tid + 256 * i] = W4[tid + 256 * i];
    }
    #pragma unroll
    for (int i = 0; i < 4; i++) {
        int f = tid + 256 * i;
        int r = f >> 4, c4 = f & 15;
        int node = row0 + r;
        float4 v = (node < n) ? ((const float4*)(x + (size_t)node * D))[c4]
                              : make_float4(0.f, 0.f, 0.f, 0.f);
        xs[r][c4 * 4 + 0] = v.x; xs[r][c4 * 4 + 1] = v.y;
        xs[r][c4 * 4 + 2] = v.z; xs[r][c4 * 4 + 3] = v.w;
    }
    __syncthreads();

    int cg = tid & 15;   // cols [cg*4, cg*4+4)
    int rg = tid >> 4;   // rows [rg*4, rg*4+4)
    float acc[4][4] = {};
    #pragma unroll 4
    for (int k = 0; k < D; k++) {
        float4 w = *(const float4*)&Ws[k * D + cg * 4];
        #pragma unroll
        for (int rr = 0; rr < 4; rr++) {
            float xv = xs[rg * 4 + rr][k];
            acc[rr][0] = fmaf(xv, w.x, acc[rr][0]);
            acc[rr][1] = fmaf(xv, w.y, acc[rr][1]);
            acc[rr][2] = fmaf(xv, w.z, acc[rr][2]);
            acc[rr][3] = fmaf(xv, w.w, acc[rr][3]);
        }
    }

    #pragma unroll
    for (int rr = 0; rr < 4; rr++) {
        int node = row0 + rg * 4 + rr;
        if (node < n) {
            float dis = rsqrtf((float)g_deg[node]);   // deg >= 1 always
            float4 v = make_float4(dis * acc[rr][0], dis * acc[rr][1],
                                   dis * acc[rr][2], dis * acc[rr][3]);
            ((float4*)(g_acc + (size_t)node * D))[cg] = v;   // self-loop term
            __half2 h0 = __floats2half2_rn(v.x, v.y);
            __half2 h1 = __floats2half2_rn(v.z, v.w);
            ((__half2*)(g_xwsh + (size_t)node * D))[cg * 2 + 0] = h0;
            ((__half2*)(g_xwsh + (size_t)node * D))[cg * 2 + 1] = h1;
            if (cg == 0) g_dis[node] = dis;
        }
    }
}

__device__ __forceinline__ void red4(float* ap, float4 v) {
    asm volatile("red.global.add.v4.f32 [%0], {%1, %2, %3, %4};"
                 :: "l"(ap), "f"(v.x), "f"(v.y), "f"(v.z), "f"(v.w)
                 : "memory");
}

__device__ __forceinline__ float4 gather_h4(const __half* base, int lane) {
    // 4 halves (8 B) per lane; convert to f32
    uint2 raw = *reinterpret_cast<const uint2*>(base + lane * 4);
    __half2 h0 = *reinterpret_cast<__half2*>(&raw.x);
    __half2 h1 = *reinterpret_cast<__half2*>(&raw.y);
    float2 f0 = __half22float2(h0);
    float2 f1 = __half22float2(h1);
    return make_float4(f0.x, f0.y, f1.x, f1.y);
}

// K4: edge scatter. 16 threads x 4 edges per thread-quad.
// Gather fp16 rows (128 B/edge, half the f32 traffic), RED f32 (exact).
__global__ void k_scatter(const int* __restrict__ ei, int E) {
    int t = blockIdx.x * blockDim.x + threadIdx.x;
    int lane = t & 15;
    int q = t >> 4;
    int e0 = q * 4;
    if (e0 >= E) return;

    if (e0 + 4 <= E) {   // fast path; E % 4 == 0
        int4 s = *reinterpret_cast<const int4*>(ei + e0);
        int4 d = *reinterpret_cast<const int4*>(ei + E + e0);
        float4 v0 = gather_h4(g_xwsh + (size_t)s.x * D, lane);
        float4 v1 = gather_h4(g_xwsh + (size_t)s.y * D, lane);
        float4 v2 = gather_h4(g_xwsh + (size_t)s.z * D, lane);
        float4 v3 = gather_h4(g_xwsh + (size_t)s.w * D, lane);
        red4(g_acc + (size_t)d.x * D + lane * 4, v0);
        red4(g_acc + (size_t)d.y * D + lane * 4, v1);
        red4(g_acc + (size_t)d.z * D + lane * 4, v2);
        red4(g_acc + (size_t)d.w * D + lane * 4, v3);
    } else {
        for (int e = e0; e < E; e++) {
            int src = ei[e], dst = ei[E + e];
            float4 v = gather_h4(g_xwsh + (size_t)src * D, lane);
            red4(g_acc + (size_t)dst * D + lane * 4, v);
        }
    }
}

// K5: out = relu(dis * acc + b), float4 vectorized
__global__ void k_final(const float* __restrict__ b, float* __restrict__ out, int n) {
    int t = blockIdx.x * blockDim.x + threadIdx.x;
    if (t >= n * (D / 4)) return;
    int node = t >> 4;
    int c4 = t & 15;
    float dis = g_dis[node];
    float4 a = reinterpret_cast<const float4*>(g_acc)[t];
    float4 bb = reinterpret_cast<const float4*>(b)[c4];
    float4 o;
    o.x = fmaxf(fmaf(dis, a.x, bb.x), 0.0f);
    o.y = fmaxf(fmaf(dis, a.y, bb.y), 0.0f);
    o.z = fmaxf(fmaf(dis, a.z, bb.z), 0.0f);
    o.w = fmaxf(fmaf(dis, a.w, bb.w), 0.0f);
    reinterpret_cast<float4*>(out)[t] = o;
}

// ---------------------------------------------------------------------------
extern "C" void kernel_launch(void* const* d_in, const int* in_sizes, int n_in,
                              void* d_out, int out_size) {
    const float* x  = (const float*)d_in[0];   // [N, 64] f32
    const int*   ei = (const int*)d_in[1];     // [2, E] int32
    const float* W  = (const float*)d_in[2];   // [64, 64] f32
    const float* b  = (const float*)d_in[3];   // [64] f32
    float* out = (float*)d_out;

    int N = in_sizes[0] / D;
    int E = in_sizes[1] / 2;
    int quads = (E + 3) / 4;

    k_deg_init<<<(N + 255) / 256, 256>>>(N);
    k_deg_count<<<(quads + 255) / 256, 256>>>(ei, E);
    k_xw<<<(N + 63) / 64, 256>>>(x, W, N);
    {
        long long work = (long long)quads * 16;
        k_scatter<<<(int)((work + 255) / 256), 256>>>(ei, E);
    }
    {
        int work = N * (D / 4);
        k_final<<<(work + 255) / 256, 256>>>(b, out, N);
    }
}

// round 9
// speedup vs baseline: 2.0495x; 1.0365x over previous
#include <cuda_runtime.h>
#include <cuda_fp16.h>
#include <cstdint>

// Problem constants (GCNLayer_12317966205308)
#define NN 50000
#define EE 800000
#define D  64

__device__ __align__(256) float  g_acc[NN * D];   // accumulator (init = self-loop term, f32)
__device__ __align__(256) __half g_xwsh[NN * D];  // fp16 copy of dis[j]*(x[j]@W) for gather
__device__ __align__(256) float  g_dis[NN];       // rsqrt(deg)
__device__ __align__(256) int    g_deg[NN];       // zero-init at load; k_xw resets to 0

// ---------------------------------------------------------------------------
// K1: edge-count histogram over dst (g_deg starts at 0: zero-init / reset by k_xw)
__global__ void k_deg_count(const int* __restrict__ ei, int E) {
    int q = blockIdx.x * blockDim.x + threadIdx.x;
    int e0 = q * 4;
    if (e0 + 4 <= E) {
        int4 d = *reinterpret_cast<const int4*>(ei + E + e0);   // E % 4 == 0
        atomicAdd(&g_deg[d.x], 1);
        atomicAdd(&g_deg[d.y], 1);
        atomicAdd(&g_deg[d.z], 1);
        atomicAdd(&g_deg[d.w], 1);
    } else {
        for (int e = e0; e < E; e++) atomicAdd(&g_deg[ei[E + e]], 1);
    }
}

__device__ __forceinline__ unsigned long long pack2(float lo, float hi) {
    unsigned long long r;
    asm("mov.b64 %0, {%1, %2};" : "=l"(r) : "f"(lo), "f"(hi));
    return r;
}
__device__ __forceinline__ void unpack2(unsigned long long p, float& lo, float& hi) {
    asm("mov.b64 {%0, %1}, %2;" : "=f"(lo), "=f"(hi) : "l"(p));
}
__device__ __forceinline__ unsigned long long fma2(unsigned long long a,
                                                   unsigned long long b,
                                                   unsigned long long c) {
    unsigned long long d;
    asm("fma.rn.f32x2 %0, %1, %2, %3;" : "=l"(d) : "l"(a), "l"(b), "l"(c));
    return d;
}

// K2: v = dis * (x @ W); acc = v (f32 self-loop term); xwsh = half(v); store dis.
// deg = g_deg + 1 (self loop); resets g_deg to 0 for the next replay.
// 256 threads/block, 64 rows/block, 4x4 tile per thread, packed f32x2 FMAs.
__global__ void __launch_bounds__(256) k_xw(const float* __restrict__ x,
                                            const float* __restrict__ W, int n) {
    __shared__ float Ws[D * D];        // [k][c]
    __shared__ float xs[64][D + 1];    // [r][k], padded
    int tid = threadIdx.x;
    int row0 = blockIdx.x * 64;

    {
        const float4* W4 = (const float4*)W;
        float4* Ws4 = (float4*)Ws;
        #pragma unroll
        for (int i = 0; i < 4; i++) Ws4[tid + 256 * i] = W4[tid + 256 * i];
    }
    #pragma unroll
    for (int i = 0; i < 4; i++) {
        int f = tid + 256 * i;
        int r = f >> 4, c4 = f & 15;
        int node = row0 + r;
        float4 v = (node < n) ? ((const float4*)(x + (size_t)node * D))[c4]
                              : make_float4(0.f, 0.f, 0.f, 0.f);
        xs[r][c4 * 4 + 0] = v.x; xs[r][c4 * 4 + 1] = v.y;
        xs[r][c4 * 4 + 2] = v.z; xs[r][c4 * 4 + 3] = v.w;
    }
    __syncthreads();

    int cg = tid & 15;   // cols [cg*4, cg*4+4)
    int rg = tid >> 4;   // rows [rg*4, rg*4+4)
    unsigned long long a01[4] = {0, 0, 0, 0};   // (c0,c1) packed per row
    unsigned long long a23[4] = {0, 0, 0, 0};   // (c2,c3) packed per row
    #pragma unroll 8
    for (int k = 0; k < D; k++) {
        float4 w = *(const float4*)&Ws[k * D + cg * 4];
        unsigned long long wxy = pack2(w.x, w.y);
        unsigned long long wzw = pack2(w.z, w.w);
        #pragma unroll
        for (int rr = 0; rr < 4; rr++) {
            float xv = xs[rg * 4 + rr][k];
            unsigned long long xp = pack2(xv, xv);
            a01[rr] = fma2(xp, wxy, a01[rr]);
            a23[rr] = fma2(xp, wzw, a23[rr]);
        }
    }

    #pragma unroll
    for (int rr = 0; rr < 4; rr++) {
        int node = row0 + rg * 4 + rr;
        if (node < n) {
            int degm1 = g_deg[node];                  // broadcast load, same half-warp
            float dis = rsqrtf((float)(degm1 + 1));   // +1 = self loop
            float4 v;
            unpack2(a01[rr], v.x, v.y);
            unpack2(a23[rr], v.z, v.w);
            v.x *= dis; v.y *= dis; v.z *= dis; v.w *= dis;
            ((float4*)(g_acc + (size_t)node * D))[cg] = v;   // self-loop term
            __half2 h0 = __floats2half2_rn(v.x, v.y);
            __half2 h1 = __floats2half2_rn(v.z, v.w);
            ((__half2*)(g_xwsh + (size_t)node * D))[cg * 2 + 0] = h0;
            ((__half2*)(g_xwsh + (size_t)node * D))[cg * 2 + 1] = h1;
            if (cg == 0) {
                g_dis[node] = dis;
                g_deg[node] = 0;    // reset for next replay (after the read above)
            }
        }
    }
}

__device__ __forceinline__ void red4(float* ap, float4 v) {
    asm volatile("red.global.add.v4.f32 [%0], {%1, %2, %3, %4};"
                 :: "l"(ap), "f"(v.x), "f"(v.y), "f"(v.z), "f"(v.w)
                 : "memory");
}

__device__ __forceinline__ float4 gather_h4(const __half* base, int lane) {
    uint2 raw = *reinterpret_cast<const uint2*>(base + lane * 4);
    __half2 h0 = *reinterpret_cast<__half2*>(&raw.x);
    __half2 h1 = *reinterpret_cast<__half2*>(&raw.y);
    float2 f0 = __half22float2(h0);
    float2 f1 = __half22float2(h1);
    return make_float4(f0.x, f0.y, f1.x, f1.y);
}

// K3: edge scatter. 16 threads x 4 edges per thread-quad.
// Gather fp16 rows (128 B/edge), RED f32 (exact).
__global__ void k_scatter(const int* __restrict__ ei, int E) {
    int t = blockIdx.x * blockDim.x + threadIdx.x;
    int lane = t & 15;
    int q = t >> 4;
    int e0 = q * 4;
    if (e0 >= E) return;

    if (e0 + 4 <= E) {   // fast path; E % 4 == 0
        int4 s = *reinterpret_cast<const int4*>(ei + e0);
        int4 d = *reinterpret_cast<const int4*>(ei + E + e0);
        float4 v0 = gather_h4(g_xwsh + (size_t)s.x * D, lane);
        float4 v1 = gather_h4(g_xwsh + (size_t)s.y * D, lane);
        float4 v2 = gather_h4(g_xwsh + (size_t)s.z * D, lane);
        float4 v3 = gather_h4(g_xwsh + (size_t)s.w * D, lane);
        red4(g_acc + (size_t)d.x * D + lane * 4, v0);
        red4(g_acc + (size_t)d.y * D + lane * 4, v1);
        red4(g_acc + (size_t)d.z * D + lane * 4, v2);
        red4(g_acc + (size_t)d.w * D + lane * 4, v3);
    } else {
        for (int e = e0; e < E; e++) {
            int src = ei[e], dst = ei[E + e];
            float4 v = gather_h4(g_xwsh + (size_t)src * D, lane);
            red4(g_acc + (size_t)dst * D + lane * 4, v);
        }
    }
}

// K4: out = relu(dis * acc + b), float4 vectorized
__global__ void k_final(const float* __restrict__ b, float* __restrict__ out, int n) {
    int t = blockIdx.x * blockDim.x + threadIdx.x;
    if (t >= n * (D / 4)) return;
    int node = t >> 4;
    int c4 = t & 15;
    float dis = g_dis[node];
    float4 a = reinterpret_cast<const float4*>(g_acc)[t];
    float4 bb = reinterpret_cast<const float4*>(b)[c4];
    float4 o;
    o.x = fmaxf(fmaf(dis, a.x, bb.x), 0.0f);
    o.y = fmaxf(fmaf(dis, a.y, bb.y), 0.0f);
    o.z = fmaxf(fmaf(dis, a.z, bb.z), 0.0f);
    o.w = fmaxf(fmaf(dis, a.w, bb.w), 0.0f);
    reinterpret_cast<float4*>(out)[t] = o;
}

// ---------------------------------------------------------------------------
extern "C" void kernel_launch(void* const* d_in, const int* in_sizes, int n_in,
                              void* d_out, int out_size) {
    const float* x  = (const float*)d_in[0];   // [N, 64] f32
    const int*   ei = (const int*)d_in[1];     // [2, E] int32
    const float* W  = (const float*)d_in[2];   // [64, 64] f32
    const float* b  = (const float*)d_in[3];   // [64] f32
    float* out = (float*)d_out;

    int N = in_sizes[0] / D;
    int E = in_sizes[1] / 2;
    int quads = (E + 3) / 4;

    k_deg_count<<<(quads + 255) / 256, 256>>>(ei, E);
    k_xw<<<(N + 63) / 64, 256>>>(x, W, N);
    {
        long long work = (long long)quads * 16;
        k_scatter<<<(int)((work + 255) / 256), 256>>>(ei, E);
    }
    {
        int work = N * (D / 4);
        k_final<<<(work + 255) / 256, 256>>>(b, out, N);
    }
}